// round 7
// baseline (speedup 1.0000x reference)
#include <cuda_runtime.h>
#include <cstdint>

#define Bv 8192
#define Mv 512
#define Ov 128

// ---- smem byte offsets ----
#define SM_XH2  0        // x sub-pass1 bf16: 256 rows * 128B = 32768
#define SM_LN   32768    // lam^T natural-k (o-row-permuted): 16384
#define SM_LP   49152    // lam^T kappa-permuted (o-row-permuted): 16384
#define SM_GAM  65536    // gam f32 [64][128] = 32768
#define SM_SRED 98304    // 16 x 64 f32 partials = 4096
#define SM_S    102400   // s[64] f32 = 256
#define SM_POOL 102656   // pooled[128] f32 = 512
#define SMEM_BYTES 103168

__device__ __forceinline__ uint32_t cvta_smem(const void* p) {
    uint32_t a;
    asm("{ .reg .u64 t; cvta.to.shared.u64 t, %1; cvt.u32.u64 %0, t; }" : "=r"(a) : "l"(p));
    return a;
}

__device__ __forceinline__ uint32_t pack_bf16x2(float lo, float hi) {
    uint32_t r;
    asm("cvt.rn.bf16x2.f32 %0, %1, %2;" : "=r"(r) : "f"(hi), "f"(lo));
    return r;
}

__device__ __forceinline__ void ldsm4(uint32_t addr, uint32_t r[4]) {
    asm volatile("ldmatrix.sync.aligned.m8n8.x4.shared.b16 {%0,%1,%2,%3}, [%4];"
        : "=r"(r[0]), "=r"(r[1]), "=r"(r[2]), "=r"(r[3]) : "r"(addr));
}

__device__ __forceinline__ void hmma(float d[4], const uint32_t a[4], const uint32_t b[2]) {
    asm volatile("mma.sync.aligned.m16n8k16.row.col.f32.bf16.bf16.f32 "
        "{%0,%1,%2,%3}, {%4,%5,%6,%7}, {%8,%9}, {%0,%1,%2,%3};"
        : "+f"(d[0]), "+f"(d[1]), "+f"(d[2]), "+f"(d[3])
        : "r"(a[0]), "r"(a[1]), "r"(a[2]), "r"(a[3]), "r"(b[0]), "r"(b[1]));
}

__device__ __forceinline__ float4 ldg_cs4(const float4* p) {
    float4 v;
    asm volatile("ld.global.cs.v4.f32 {%0,%1,%2,%3}, [%4];"
        : "=f"(v.x), "=f"(v.y), "=f"(v.z), "=f"(v.w) : "l"(p));
    return v;
}
__device__ __forceinline__ void stg_cs4(float* p, float a, float b, float c, float d) {
    asm volatile("st.global.cs.v4.f32 [%0], {%1,%2,%3,%4};"
        :: "l"(p), "f"(a), "f"(b), "f"(c), "f"(d) : "memory");
}

__device__ __forceinline__ void red4(float4& v, int mask) {
    v.x += __shfl_xor_sync(0xffffffffu, v.x, mask);
    v.y += __shfl_xor_sync(0xffffffffu, v.y, mask);
    v.z += __shfl_xor_sync(0xffffffffu, v.z, mask);
    v.w += __shfl_xor_sync(0xffffffffu, v.w, mask);
}

extern __shared__ char smem[];

// One MMA half (32 rows x 128 cols) with A in registers; lam copy selected by lam_off.
__device__ __forceinline__ void mma_half(
    const uint32_t sb, const char* smemc, float* outb,
    const uint32_t afr[4][2][4], uint32_t lam_off,
    int mbase, int g, int tg, int bo, int bcs, int bsw, bool gate)
{
    #pragma unroll 1
    for (int nh = 0; nh < 2; nh++) {
        const int o0 = nh * 64;
        float acc[2][8][4];
        #pragma unroll
        for (int i = 0; i < 2; i++)
            #pragma unroll
            for (int j = 0; j < 8; j++)
                #pragma unroll
                for (int c = 0; c < 4; c++)
                    acc[i][j][c] = 0.f;

        #pragma unroll
        for (int k = 0; k < 4; k++)
            #pragma unroll
            for (int np = 0; np < 4; np++) {
                uint32_t bf[4];
                ldsm4(sb + lam_off + (uint32_t)((o0 + np * 16 + bo) * 128
                        + ((((k << 1) | bcs) ^ bsw) << 4)), bf);
                hmma(acc[0][2 * np],     afr[k][0], bf);
                hmma(acc[0][2 * np + 1], afr[k][0], bf + 2);
                hmma(acc[1][2 * np],     afr[k][1], bf);
                hmma(acc[1][2 * np + 1], afr[k][1], bf + 2);
            }

        if (gate && nh == 0)
            asm volatile("bar.sync 2, 256;" ::: "memory");

        #pragma unroll
        for (int np = 0; np < 4; np++) {
            const int col = o0 + np * 16 + 4 * tg;
            const float4 pl = *(const float4*)(smemc + SM_POOL + col * 4);
            #pragma unroll
            for (int mt = 0; mt < 2; mt++) {
                const float* a0 = acc[mt][2 * np];
                const float* a1 = acc[mt][2 * np + 1];
                float* r0 = outb + (size_t)(mbase + mt * 16 + g) * Ov + col;
                stg_cs4(r0,
                        fmaxf(a0[0] - pl.x, 0.f), fmaxf(a0[1] - pl.y, 0.f),
                        fmaxf(a1[0] - pl.z, 0.f), fmaxf(a1[1] - pl.w, 0.f));
                stg_cs4(r0 + 8 * Ov,
                        fmaxf(a0[2] - pl.x, 0.f), fmaxf(a0[3] - pl.y, 0.f),
                        fmaxf(a1[2] - pl.z, 0.f), fmaxf(a1[3] - pl.w, 0.f));
            }
        }
    }
}

__global__ __launch_bounds__(256, 2)
void eq_mma4_kernel(const float* __restrict__ x,
                    const float* __restrict__ lam,
                    const float* __restrict__ gam,
                    float* __restrict__ out)
{
    const uint32_t sb = cvta_smem(smem);
    const int t = threadIdx.x;
    const int b = blockIdx.x;
    const int w = t >> 5, lane = t & 31, g = lane >> 2, tg = lane & 3;
    const float* xb = x + (size_t)b * (Mv * 64);
    const int m0 = w * 64;

    // ---- x sub-pass1 (rows m0+32..m0+63): global -> bf16 smem + sums ----
    float4 sB = make_float4(0.f, 0.f, 0.f, 0.f);
    {
        const int f4 = lane & 15, rp = lane >> 4;
        const int chunk = f4 >> 1, half = f4 & 1;
        #pragma unroll 4
        for (int i = 0; i < 16; i++) {
            const int mr = rp + 2 * i;     // 0..31 within sub-pass
            const float4 v = ldg_cs4((const float4*)(xb + (size_t)(m0 + 32 + mr) * 64) + f4);
            sB.x += v.x; sB.y += v.y; sB.z += v.z; sB.w += v.w;
            const uint32_t h01 = pack_bf16x2(v.x, v.y);
            const uint32_t h23 = pack_bf16x2(v.z, v.w);
            const uint32_t off = (uint32_t)((w * 32 + mr) * 128
                + ((chunk ^ (mr & 7)) << 4) + half * 8);
            *(uint2*)(smem + SM_XH2 + off) = make_uint2(h01, h23);
        }
    }

    // ---- x sub-pass0 (rows m0..m0+31): global -> A fragments (kappa-permuted) + sums ----
    uint32_t afr[4][2][4];
    float4 sA[4];
    #pragma unroll
    for (int k = 0; k < 4; k++) sA[k] = make_float4(0.f, 0.f, 0.f, 0.f);
    #pragma unroll
    for (int k = 0; k < 4; k++)
        #pragma unroll
        for (int mt = 0; mt < 2; mt++) {
            const float* base = xb + (size_t)(m0 + mt * 16 + g) * 64 + 16 * k + 4 * tg;
            const float4 va = ldg_cs4((const float4*)base);
            const float4 vb = ldg_cs4((const float4*)(base + 8 * 64));
            sA[k].x += va.x + vb.x; sA[k].y += va.y + vb.y;
            sA[k].z += va.z + vb.z; sA[k].w += va.w + vb.w;
            afr[k][mt][0] = pack_bf16x2(va.x, va.y);
            afr[k][mt][1] = pack_bf16x2(vb.x, vb.y);
            afr[k][mt][2] = pack_bf16x2(va.z, va.w);
            afr[k][mt][3] = pack_bf16x2(vb.z, vb.w);
        }

    // ---- lam: both copies (natural-k and kappa-permuted), o-row-permuted ----
    {
        const int o = t & 127;
        const int r15 = o & 15;
        const int orow = (o & ~15) | (((r15 & 2) << 2) | ((r15 >> 2) << 1) | (r15 & 1));
        const int q = t >> 7;
        #pragma unroll 4
        for (int j = 0; j < 16; j++) {
            const int fp = q * 16 + j;    // real f-pair 0..31
            const float v0 = lam[(2 * fp) * Ov + o];
            const float v1 = lam[(2 * fp + 1) * Ov + o];
            const uint32_t h = pack_bf16x2(v0, v1);
            const uint32_t offN = (uint32_t)(orow * 128
                + (((fp >> 2) ^ (orow & 7)) << 4) + (fp & 3) * 4);
            *(uint32_t*)(smem + SM_LN + offN) = h;
            // kappa slot: fp = 8ks + r, r = 2tg'+h' -> slot = 8ks + tg' + 4h'
            const int ks = fp >> 3, rr = fp & 7;
            const int fps = 8 * ks + (rr >> 1) + 4 * (rr & 1);
            const uint32_t offP = (uint32_t)(orow * 128
                + (((fps >> 2) ^ (orow & 7)) << 4) + (fps & 3) * 4);
            *(uint32_t*)(smem + SM_LP + offP) = h;
        }
    }

    // ---- gam -> smem (straight copy) ----
    {
        const float4* gg = (const float4*)gam;
        float4* gs = (float4*)(smem + SM_GAM);
        #pragma unroll
        for (int i = 0; i < 8; i++) gs[t + 256 * i] = gg[t + 256 * i];
    }

    // ---- reduce column sums, write per-warp partials ----
    #pragma unroll
    for (int k = 0; k < 4; k++) { red4(sA[k], 4); red4(sA[k], 8); red4(sA[k], 16); }
    red4(sB, 16);
    if (lane < 4) {
        #pragma unroll
        for (int k = 0; k < 4; k++)
            *(float4*)(smem + SM_SRED + ((2 * w) * 64 + 16 * k + 4 * lane) * 4) = sA[k];
    }
    if (lane < 16)
        *(float4*)(smem + SM_SRED + ((2 * w + 1) * 64 + 4 * lane) * 4) = sB;

    __syncthreads();

    // ---- pooled (warps 0-3) producer; warps 4-7 go straight to MMA ----
    if (t < 128) {
        if (t < 64) {
            float s = 0.f;
            #pragma unroll
            for (int r = 0; r < 16; r++)
                s += *(const float*)(smem + SM_SRED + (r * 64 + t) * 4);
            *(float*)(smem + SM_S + t * 4) = s;
        }
        asm volatile("bar.sync 1, 128;" ::: "memory");
        float p = 0.f;
        #pragma unroll
        for (int f = 0; f < 64; f++)
            p += *(const float*)(smem + SM_S + f * 4)
               * *(const float*)(smem + SM_GAM + (f * 128 + t) * 4);
        *(float*)(smem + SM_POOL + t * 4) = p;
        asm volatile("bar.sync 3, 128;" ::: "memory");
        asm volatile("bar.arrive 2, 256;" ::: "memory");
    }

    const int bo = (lane & 7) | ((lane & 16) >> 1);
    const int bcs = (lane >> 3) & 1;
    const int bsw = bo & 7;
    float* outb = out + (size_t)b * (Mv * Ov);
    const bool gate = (t >= 128);   // consumers wait for pooled before first store

    // ---- MMA half 0: direct-register A, kappa-permuted lam ----
    mma_half(sb, smem, outb, afr, SM_LP, m0, g, tg, bo, bcs, bsw, gate);

    // ---- MMA half 1: smem A via ldmatrix, natural lam ----
    const int am = lane & 15, acs = lane >> 4, asw = am & 7;
    uint32_t ald[4][2][4];
    #pragma unroll
    for (int k = 0; k < 4; k++) {
        const uint32_t aadr = sb + SM_XH2 + (uint32_t)((w * 32 + am) * 128
                            + ((((k << 1) | acs) ^ asw) << 4));
        ldsm4(aadr, ald[k][0]);
        ldsm4(aadr + 16 * 128, ald[k][1]);
    }
    mma_half(sb, smem, outb, ald, SM_LN, m0 + 32, g, tg, bo, bcs, bsw, false);
}

extern "C" void kernel_launch(void* const* d_in, const int* in_sizes, int n_in,
                              void* d_out, int out_size)
{
    (void)in_sizes; (void)n_in; (void)out_size;
    const float* x   = (const float*)d_in[0];
    const float* lam = (const float*)d_in[1];
    const float* gam = (const float*)d_in[2];
    float* out = (float*)d_out;

    cudaFuncSetAttribute(eq_mma4_kernel, cudaFuncAttributeMaxDynamicSharedMemorySize,
                         SMEM_BYTES);
    eq_mma4_kernel<<<Bv, 256, SMEM_BYTES>>>(x, lam, gam, out);
}

// round 8
// speedup vs baseline: 1.1392x; 1.1392x over previous
#include <cuda_runtime.h>
#include <cstdint>

#define Bv 8192
#define Mv 512
#define Ov 128

// ---- smem byte offsets ----
#define SM_XH   0        // x bf16: 512 rows * 128B (chunk-XOR swizzled) = 65536
#define SM_LN   65536    // lam^T bf16 (o-row-permuted): 128 rows * 128B = 16384
#define SM_SRED 81920    // 8 warps x 64 f32 column-sum partials = 2048
#define SM_S    83968    // s[64] f32 = 256
#define SM_POOL 84224    // pooled[128] f32 = 512
#define SMEM_BYTES 84736

__device__ __forceinline__ uint32_t cvta_smem(const void* p) {
    uint32_t a;
    asm("{ .reg .u64 t; cvta.to.shared.u64 t, %1; cvt.u32.u64 %0, t; }" : "=r"(a) : "l"(p));
    return a;
}

__device__ __forceinline__ uint32_t pack_bf16x2(float lo, float hi) {
    uint32_t r;
    asm("cvt.rn.bf16x2.f32 %0, %1, %2;" : "=r"(r) : "f"(hi), "f"(lo));
    return r;
}

__device__ __forceinline__ void ldsm4(uint32_t addr, uint32_t r[4]) {
    asm volatile("ldmatrix.sync.aligned.m8n8.x4.shared.b16 {%0,%1,%2,%3}, [%4];"
        : "=r"(r[0]), "=r"(r[1]), "=r"(r[2]), "=r"(r[3]) : "r"(addr));
}

__device__ __forceinline__ void hmma(float d[4], const uint32_t a[4], const uint32_t b[2]) {
    asm volatile("mma.sync.aligned.m16n8k16.row.col.f32.bf16.bf16.f32 "
        "{%0,%1,%2,%3}, {%4,%5,%6,%7}, {%8,%9}, {%0,%1,%2,%3};"
        : "+f"(d[0]), "+f"(d[1]), "+f"(d[2]), "+f"(d[3])
        : "r"(a[0]), "r"(a[1]), "r"(a[2]), "r"(a[3]), "r"(b[0]), "r"(b[1]));
}

__device__ __forceinline__ float4 ldg_cs4(const float4* p) {
    float4 v;
    asm volatile("ld.global.cs.v4.f32 {%0,%1,%2,%3}, [%4];"
        : "=f"(v.x), "=f"(v.y), "=f"(v.z), "=f"(v.w) : "l"(p));
    return v;
}
__device__ __forceinline__ void stg_cs4(float* p, float a, float b, float c, float d) {
    asm volatile("st.global.cs.v4.f32 [%0], {%1,%2,%3,%4};"
        :: "l"(p), "f"(a), "f"(b), "f"(c), "f"(d) : "memory");
}

__device__ __forceinline__ void red4(float4& v, int mask) {
    v.x += __shfl_xor_sync(0xffffffffu, v.x, mask);
    v.y += __shfl_xor_sync(0xffffffffu, v.y, mask);
    v.z += __shfl_xor_sync(0xffffffffu, v.z, mask);
    v.w += __shfl_xor_sync(0xffffffffu, v.w, mask);
}

extern __shared__ char smem[];

__global__ __launch_bounds__(256, 2)
void eq_mma5_kernel(const float* __restrict__ x,
                    const float* __restrict__ lam,
                    const float* __restrict__ gam,
                    float* __restrict__ out)
{
    const uint32_t sb = cvta_smem(smem);
    const int t = threadIdx.x;
    const int b = blockIdx.x;
    const int w = t >> 5, lane = t & 31, g = lane >> 2, tg = lane & 3;

    // ---- lam^T -> bf16 smem, o-row-permuted within each 16-row group ----
    {
        const int o = t & 127;
        const int r15 = o & 15;
        const int orow = (o & ~15) | (((r15 & 2) << 2) | ((r15 >> 2) << 1) | (r15 & 1));
        const int q = t >> 7;
        #pragma unroll 4
        for (int j = 0; j < 16; j++) {
            const int fp = q * 16 + j;
            const float v0 = lam[(2 * fp) * Ov + o];
            const float v1 = lam[(2 * fp + 1) * Ov + o];
            const uint32_t h = pack_bf16x2(v0, v1);
            const uint32_t off = (uint32_t)(orow * 128
                + (((fp >> 2) ^ (orow & 7)) << 4) + (fp & 3) * 4);
            *(uint32_t*)(smem + SM_LN + off) = h;
        }
    }
    __syncthreads();   // cheap: only lam (L2-resident) behind it

    // ---- per-warp x staging: warp w owns rows 64w..64w+63 ----
    {
        const float4* xg = (const float4*)(x + (size_t)b * (Mv * 64));
        const int f4 = lane & 15, rp = lane >> 4;
        const int chunk = f4 >> 1, half = f4 & 1;
        float4 s4 = make_float4(0.f, 0.f, 0.f, 0.f);
        #pragma unroll 8
        for (int i = 0; i < 32; i++) {
            const int m = w * 64 + 2 * i + rp;
            const float4 v = ldg_cs4(&xg[m * 16 + f4]);
            s4.x += v.x; s4.y += v.y; s4.z += v.z; s4.w += v.w;
            const uint32_t h01 = pack_bf16x2(v.x, v.y);
            const uint32_t h23 = pack_bf16x2(v.z, v.w);
            const uint32_t off = (uint32_t)(m * 128 + ((chunk ^ (m & 7)) << 4) + half * 8);
            *(uint2*)(smem + SM_XH + off) = make_uint2(h01, h23);
        }
        red4(s4, 16);   // combine rp=0/1 partners -> full warp column sums
        if (lane < 16)
            *(float4*)(smem + SM_SRED + (w * 64 + f4 * 4) * 4) = s4;
    }
    __syncwarp();

    // ---- pooled pipeline: warp 0 produces, others just signal + proceed ----
    if (w == 0) {
        asm volatile("bar.sync 1, 256;" ::: "memory");   // wait all warps' sred
        float sv0 = 0.f, sv1 = 0.f;
        #pragma unroll
        for (int r = 0; r < 8; r++) {
            sv0 += *(const float*)(smem + SM_SRED + (r * 64 + lane) * 4);
            sv1 += *(const float*)(smem + SM_SRED + (r * 64 + lane + 32) * 4);
        }
        *(float*)(smem + SM_S + lane * 4) = sv0;
        *(float*)(smem + SM_S + (lane + 32) * 4) = sv1;
        __syncwarp();
        float4 p = make_float4(0.f, 0.f, 0.f, 0.f);
        const float4* gp = (const float4*)gam + lane;   // gam[f][4*lane..+3], L2-hit
        #pragma unroll 8
        for (int f = 0; f < 64; f++) {
            const float sf = *(const float*)(smem + SM_S + f * 4);
            const float4 gv = gp[f * 32];
            p.x += sf * gv.x; p.y += sf * gv.y;
            p.z += sf * gv.z; p.w += sf * gv.w;
        }
        *(float4*)(smem + SM_POOL + lane * 16) = p;
        __syncwarp();
        asm volatile("bar.arrive 2, 256;" ::: "memory"); // release consumers
    } else {
        asm volatile("bar.arrive 1, 256;" ::: "memory");
    }

    // ---- MMA: per-warp 64 rows x 128 cols, two 32-row sub-passes ----
    const int am = lane & 15, acs = lane >> 4, asw = am & 7;
    const int bo = (lane & 7) | ((lane & 16) >> 1);
    const int bcs = (lane >> 3) & 1, bsw = bo & 7;
    const float* poolp = (const float*)(smem + SM_POOL);
    float* outb = out + (size_t)b * (Mv * Ov);

    #pragma unroll 1
    for (int mp = 0; mp < 2; mp++) {
        const int m0 = w * 64 + mp * 32;
        const uint32_t arow_off = (uint32_t)((m0 + am) * 128);

        uint32_t afr[4][2][4];
        #pragma unroll
        for (int k = 0; k < 4; k++) {
            const uint32_t aadr = sb + SM_XH + arow_off
                                + (uint32_t)((((k << 1) | acs) ^ asw) << 4);
            ldsm4(aadr, afr[k][0]);
            ldsm4(aadr + 16 * 128, afr[k][1]);
        }

        #pragma unroll 1
        for (int nh = 0; nh < 2; nh++) {
            const int o0 = nh * 64;
            float acc[2][8][4];
            #pragma unroll
            for (int i = 0; i < 2; i++)
                #pragma unroll
                for (int j = 0; j < 8; j++)
                    #pragma unroll
                    for (int c = 0; c < 4; c++)
                        acc[i][j][c] = 0.f;

            #pragma unroll
            for (int k = 0; k < 4; k++)
                #pragma unroll
                for (int np = 0; np < 4; np++) {
                    uint32_t bf[4];
                    ldsm4(sb + SM_LN + (uint32_t)((o0 + np * 16 + bo) * 128
                            + ((((k << 1) | bcs) ^ bsw) << 4)), bf);
                    hmma(acc[0][2 * np],     afr[k][0], bf);
                    hmma(acc[0][2 * np + 1], afr[k][0], bf + 2);
                    hmma(acc[1][2 * np],     afr[k][1], bf);
                    hmma(acc[1][2 * np + 1], afr[k][1], bf + 2);
                }

            // consumers wait for pooled exactly once, right before first store
            if (w != 0 && mp == 0 && nh == 0)
                asm volatile("bar.sync 2, 256;" ::: "memory");

            #pragma unroll
            for (int np = 0; np < 4; np++) {
                const int col = o0 + np * 16 + 4 * tg;
                const float4 pl = *(const float4*)&poolp[col];
                #pragma unroll
                for (int mt = 0; mt < 2; mt++) {
                    const float* a0 = acc[mt][2 * np];
                    const float* a1 = acc[mt][2 * np + 1];
                    float* r0 = outb + (size_t)(m0 + mt * 16 + g) * Ov + col;
                    stg_cs4(r0,
                            fmaxf(a0[0] - pl.x, 0.f), fmaxf(a0[1] - pl.y, 0.f),
                            fmaxf(a1[0] - pl.z, 0.f), fmaxf(a1[1] - pl.w, 0.f));
                    stg_cs4(r0 + 8 * Ov,
                            fmaxf(a0[2] - pl.x, 0.f), fmaxf(a0[3] - pl.y, 0.f),
                            fmaxf(a1[2] - pl.z, 0.f), fmaxf(a1[3] - pl.w, 0.f));
                }
            }
        }
    }
}

extern "C" void kernel_launch(void* const* d_in, const int* in_sizes, int n_in,
                              void* d_out, int out_size)
{
    (void)in_sizes; (void)n_in; (void)out_size;
    const float* x   = (const float*)d_in[0];
    const float* lam = (const float*)d_in[1];
    const float* gam = (const float*)d_in[2];
    float* out = (float*)d_out;

    cudaFuncSetAttribute(eq_mma5_kernel, cudaFuncAttributeMaxDynamicSharedMemorySize,
                         SMEM_BYTES);
    eq_mma5_kernel<<<Bv, 256, SMEM_BYTES>>>(x, lam, gam, out);
}